// round 17
// baseline (speedup 1.0000x reference)
#include <cuda_runtime.h>
#include <math.h>
#include <stdint.h>

#define BB   32
#define TT   128
#define G3   1536
#define NCTA 128

__device__ float g_e   [BB*TT*512];
__device__ int   g_mask[BB*TT];
__device__ float g_xp0 [BB*TT*G3];
__device__ float g_xp1 [BB*TT*G3];
__device__ float g_hcat[BB*TT*1024];
__device__ float g_y   [BB*TT*512];
__device__ float g_h   [8*512*16];        // [sub*2+phase][k][b]  (max NB=16)
__device__ unsigned int g_bar[4*128];
__device__ int   g_is64;

__device__ __forceinline__ float sigf(float x){ return 1.f/(1.f + __expf(-x)); }

__global__ void prep_kernel(const int* xw){
    __shared__ int s_ok;
    if (threadIdx.x == 0) s_ok = 1;
    __syncthreads();
    int bad = 0;
    for (int i = threadIdx.x; i < 2040; i += blockDim.x)
        if (xw[2*i + 1] != 0) bad = 1;
    if (bad) atomicExch(&s_ok, 0);
    __syncthreads();
    if (threadIdx.x == 0) g_is64 = s_ok;
    for (int i = threadIdx.x; i < 4*128; i += blockDim.x) g_bar[i] = 0u;
}

__global__ void embed_kernel(const int* xw, const float* E){
    int i = blockIdx.x;
    int tok = g_is64 ? xw[2*i] : xw[i];
    if (threadIdx.x == 0) g_mask[i] = (tok != 0);
    const float4* src = (const float4*)(E + (size_t)tok * 512);
    float4* dst = (float4*)(g_e + (size_t)i * 512);
    dst[threadIdx.x] = src[threadIdx.x];
}

__global__ __launch_bounds__(256)
void gemm_kernel(const float* A, int lda, int K,
                 const float* Bm, const float* bias, float* C){
    __shared__ __align__(16) float As[8*128];
    __shared__ __align__(16) float Bs[8*128];
    int tid = threadIdx.x;
    int m0 = blockIdx.y * 128, n0 = blockIdx.x * 128;
    int tx = tid & 15, ty = tid >> 4;
    int arow = tid >> 1, akq = (tid & 1) * 4;
    int bkr  = tid >> 5, bnc = (tid & 31) * 4;
    const float* Aptr = A + (size_t)(m0 + arow) * lda + akq;
    const float* Bptr = Bm + (size_t)bkr * G3 + n0 + bnc;

    float acc[8][8];
    #pragma unroll
    for (int i = 0; i < 8; i++)
        #pragma unroll
        for (int j = 0; j < 8; j++) acc[i][j] = 0.f;

    int KT = K >> 3;
    float4 ra = *(const float4*)(Aptr);
    float4 rb = *(const float4*)(Bptr);
    for (int kt = 0; kt < KT; kt++){
        As[(akq+0)*128 + arow] = ra.x;
        As[(akq+1)*128 + arow] = ra.y;
        As[(akq+2)*128 + arow] = ra.z;
        As[(akq+3)*128 + arow] = ra.w;
        *(float4*)(Bs + bkr*128 + bnc) = rb;
        __syncthreads();
        if (kt + 1 < KT){
            ra = *(const float4*)(Aptr + (kt+1)*8);
            rb = *(const float4*)(Bptr + (size_t)(kt+1)*8*G3);
        }
        #pragma unroll
        for (int kk = 0; kk < 8; kk++){
            float a[8], b[8];
            *(float4*)(a)   = *(const float4*)(As + kk*128 + ty*8);
            *(float4*)(a+4) = *(const float4*)(As + kk*128 + ty*8 + 4);
            *(float4*)(b)   = *(const float4*)(Bs + kk*128 + tx*8);
            *(float4*)(b+4) = *(const float4*)(Bs + kk*128 + tx*8 + 4);
            #pragma unroll
            for (int i = 0; i < 8; i++)
                #pragma unroll
                for (int j = 0; j < 8; j++) acc[i][j] += a[i]*b[j];
        }
        __syncthreads();
    }
    float bb[8];
    #pragma unroll
    for (int j = 0; j < 8; j++) bb[j] = bias[n0 + tx*8 + j];
    #pragma unroll
    for (int i = 0; i < 8; i++){
        float* crow = C + (size_t)(m0 + ty*8 + i)*G3 + n0 + tx*8;
        float4 o0, o1;
        o0.x = acc[i][0]+bb[0]; o0.y = acc[i][1]+bb[1]; o0.z = acc[i][2]+bb[2]; o0.w = acc[i][3]+bb[3];
        o1.x = acc[i][4]+bb[4]; o1.y = acc[i][5]+bb[5]; o1.z = acc[i][6]+bb[6]; o1.w = acc[i][7]+bb[7];
        *(float4*)(crow)     = o0;
        *(float4*)(crow + 4) = o1;
    }
}

// 2-D persistent scan, warp-decoupled exchange:
// 128 CTAs = 32 unit-groups (16 units) x 4 subgroups. Each dot warp polls only
// its 4 producer CTAs, stages its own 1/8 k-slice, and computes. h_prev lives
// in gate-thread registers. Flags published with st.release.gpu.
template<int BIDI>
__global__ __launch_bounds__(256)
void scan_kernel(const float* xpF, const float* UF, const float* brF, float* yF, int yoffF,
                 const float* xpB, const float* UB, const float* brB, float* yB, int yoffB,
                 int ystride, unsigned int* flag, int write_hT)
{
    constexpr int NB  = BIDI ? 16 : 8;
    constexpr int HB  = NB / 2;
    constexpr int NBP = NB + 1;
    extern __shared__ __align__(16) float sm[];
    float* Us  = sm;                       // [512][48]
    float* hs  = Us + 512*48;              // [512][NB]
    float* ps  = hs + 512*NB;              // [8][48*NBP]
    float* brs = ps + 8*48*NBP;            // [48]

    int tid = threadIdx.x;
    int bid = blockIdx.x;
    int sub = bid >> 5;
    int dir = BIDI ? (sub >> 1) : 0;
    int bg0 = BIDI ? ((sub & 1) * 16) : (sub * 8);
    int u0  = (bid & 31) * 16;
    int rev = BIDI ? dir : 0;

    const float* xp = dir ? xpB : xpF;
    const float* Uw = dir ? UB  : UF;
    const float* br = dir ? brB : brF;
    float*       yp = dir ? yB  : yF;
    int        yoff = dir ? yoffB : yoffF;

    for (int idx = tid; idx < 512*48; idx += 256){
        int k = idx / 48, c = idx % 48;
        int col = (c >> 4)*512 + u0 + (c & 15);
        Us[idx] = Uw[(size_t)k*G3 + col];
    }
    if (tid < 48) brs[tid] = br[(tid >> 4)*512 + u0 + (tid & 15)];
    __syncthreads();

    int ks   = tid >> 5;                   // warp id == k-chunk
    int lane = tid & 31;
    int c0   = (lane >> 1) * 3;
    int b0   = (lane & 1) * HB;

    int gu  = tid & 15, gbr = tid >> 4;
    bool gact = (tid < 16*NB);

    float bz = 0.f, brr = 0.f, bh = 0.f;
    if (gact){ bz = brs[gu]; brr = brs[16 + gu]; bh = brs[32 + gu]; }
    float hreg = 0.f;                      // this thread's h_prev

    const unsigned int* myflags = flag + sub*32 + 4*ks;   // 4 producer CTAs for this warp
    unsigned int* ownflag = flag + sub*32 + (bid & 31);

    for (int t = 0; t < TT; t++){
        // prefetch x + mask (independent of flags)
        float px0 = 0.f, px1 = 0.f, px2 = 0.f; int pm = 0, tq = 0, gb = 0;
        if (gact){
            tq = rev ? (TT - 1 - t) : t;
            gb = bg0 + gbr;
            const float* xr = xp + (size_t)(gb*TT + tq)*G3 + u0 + gu;
            px0 = __ldg(xr); px1 = __ldg(xr + 512); px2 = __ldg(xr + 1024);
            pm  = g_mask[gb*TT + tq];
        }

        if (t > 0){
            // ---- per-warp: wait for 4 producers, stage own k-slice, dot ----
            if (lane < 4){
                unsigned v;
                do {
                    asm volatile("ld.relaxed.gpu.global.u32 %0, [%1];"
                                 : "=r"(v) : "l"(myflags + lane) : "memory");
                } while (v < (unsigned)t);
                asm volatile("fence.acq_rel.gpu;" ::: "memory");
            }
            __syncwarp();

            int ph = (t + 1) & 1;
            {
                const float4* src = (const float4*)&g_h[(size_t)(sub*2 + ph)*512*NB] + ks*(64*NB/4);
                float4* dst = (float4*)hs + ks*(64*NB/4);
                #pragma unroll
                for (int r = lane; r < 64*NB/4; r += 32) dst[r] = __ldcg(src + r);
            }
            __syncwarp();

            float acc[3][HB];
            #pragma unroll
            for (int i = 0; i < 3; i++)
                #pragma unroll
                for (int j = 0; j < HB; j++) acc[i][j] = 0.f;
            const float*  up  = Us + ks*(64*48) + c0;
            const float4* hp4 = (const float4*)(hs + ks*64*NB + b0);
            #pragma unroll 4
            for (int k = 0; k < 64; k++){
                float uv0 = up[k*48], uv1 = up[k*48 + 1], uv2 = up[k*48 + 2];
                float hv[HB];
                *(float4*)hv = hp4[k*(NB/4)];
                if (HB == 8) *(float4*)(hv + 4) = hp4[k*(NB/4) + 1];
                #pragma unroll
                for (int j = 0; j < HB; j++){
                    acc[0][j] += uv0 * hv[j];
                    acc[1][j] += uv1 * hv[j];
                    acc[2][j] += uv2 * hv[j];
                }
            }
            float* pr = ps + ks*(48*NBP) + c0*NBP + b0;
            #pragma unroll
            for (int i = 0; i < 3; i++)
                #pragma unroll
                for (int j = 0; j < HB; j++) pr[i*NBP + j] = acc[i][j];
        }
        __syncthreads();

        if (gact){
            float rz = bz, rr = brr, rh = bh;
            if (t > 0){
                #pragma unroll
                for (int q = 0; q < 8; q++){
                    const float* pq = ps + q*(48*NBP);
                    rz += pq[(0  + gu)*NBP + gbr];
                    rr += pq[(16 + gu)*NBP + gbr];
                    rh += pq[(32 + gu)*NBP + gbr];
                }
            }
            float z  = sigf(px0 + rz);
            float rg = sigf(px1 + rr);
            float hh = sigf(px2 + rg*rh);
            float hprev = hreg;
            float hn = z*hprev + (1.f - z)*hh;
            if (!pm) hn = hprev;
            hreg = hn;
            g_h[(size_t)(sub*2 + (t & 1))*512*NB + (u0 + gu)*NB + gbr] = hn;
            yp[(size_t)(gb*TT + tq)*ystride + yoff + u0 + gu] = hn;
            if (write_hT && t == TT - 1)
                yp[(size_t)BB*TT*ystride + gb*512 + u0 + gu] = hn;
        }
        __syncthreads();

        if (t < TT - 1 && tid == 0){
            asm volatile("st.release.gpu.global.u32 [%0], %1;"
                         :: "l"(ownflag), "r"((unsigned)(t + 1)) : "memory");
        }
    }
}

extern "C" void kernel_launch(void* const* d_in, const int* in_sizes, int n_in,
                              void* d_out, int out_size)
{
    const int*   x     = (const int*)  d_in[0];
    const float* E     = (const float*)d_in[2];
    const float* W_fw  = (const float*)d_in[3];
    const float* U_fw  = (const float*)d_in[4];
    const float* b_fw  = (const float*)d_in[5];
    const float* W_bw  = (const float*)d_in[6];
    const float* U_bw  = (const float*)d_in[7];
    const float* b_bw  = (const float*)d_in[8];
    const float* W_m0  = (const float*)d_in[9];
    const float* U_m0  = (const float*)d_in[10];
    const float* b_m0  = (const float*)d_in[11];
    const float* W_m1  = (const float*)d_in[12];
    const float* U_m1  = (const float*)d_in[13];
    const float* b_m1  = (const float*)d_in[14];
    const float* W_top = (const float*)d_in[15];
    const float* U_top = (const float*)d_in[16];
    const float* b_top = (const float*)d_in[17];
    float* out = (float*)d_out;

    const int SMEM2 = (512*48 + 512*16 + 8*48*17 + 48) * 4;
    const int SMEM1 = (512*48 + 512*8  + 8*48*9  + 48) * 4;
    cudaFuncSetAttribute((const void*)scan_kernel<1>,
                         cudaFuncAttributeMaxDynamicSharedMemorySize, SMEM2);
    cudaFuncSetAttribute((const void*)scan_kernel<0>,
                         cudaFuncAttributeMaxDynamicSharedMemorySize, SMEM1);

    float *e, *xp0, *xp1, *hcat, *y; unsigned int* bar;
    cudaGetSymbolAddress((void**)&e,    g_e);
    cudaGetSymbolAddress((void**)&xp0,  g_xp0);
    cudaGetSymbolAddress((void**)&xp1,  g_xp1);
    cudaGetSymbolAddress((void**)&hcat, g_hcat);
    cudaGetSymbolAddress((void**)&y,    g_y);
    cudaGetSymbolAddress((void**)&bar,  g_bar);

    int write_hT = (out_size >= BB*TT*512 + BB*512) ? 1 : 0;

    prep_kernel<<<1, 256>>>(x);
    embed_kernel<<<BB*TT, 128>>>(x, E);

    dim3 gg(G3/128, (BB*TT)/128);
    gemm_kernel<<<gg, 256>>>(e, 512, 512, W_fw, b_fw, xp0);
    gemm_kernel<<<gg, 256>>>(e, 512, 512, W_bw, b_bw, xp1);

    scan_kernel<1><<<NCTA, 256, SMEM2>>>(
        xp0, U_fw, b_fw + G3, hcat, 0,
        xp1, U_bw, b_bw + G3, hcat, 512,
        1024, bar + 0, 0);

    gemm_kernel<<<gg, 256>>>(hcat, 1024, 1024, W_m0, b_m0, xp0);
    scan_kernel<0><<<NCTA, 256, SMEM1>>>(
        xp0, U_m0, b_m0 + G3, y, 0,
        xp0, U_m0, b_m0 + G3, y, 0,
        512, bar + 128, 0);

    gemm_kernel<<<gg, 256>>>(y, 512, 512, W_m1, b_m1, xp0);
    scan_kernel<0><<<NCTA, 256, SMEM1>>>(
        xp0, U_m1, b_m1 + G3, y, 0,
        xp0, U_m1, b_m1 + G3, y, 0,
        512, bar + 256, 0);

    gemm_kernel<<<gg, 256>>>(y, 512, 512, W_top, b_top, xp0);
    scan_kernel<0><<<NCTA, 256, SMEM1>>>(
        xp0, U_top, b_top + G3, out, 0,
        xp0, U_top, b_top + G3, out, 0,
        512, bar + 384, write_hT);
}